// round 3
// baseline (speedup 1.0000x reference)
#include <cuda_runtime.h>
#include <math.h>

#define SEQ   2048
#define BATCH 64
#define INP   256
#define HID   256

typedef unsigned long long ull;

// ---------- packed f32x2 helpers (Blackwell FFMA2 path, PTX-only) ----------
__device__ __forceinline__ void ffma2(ull& d, ull a, ull b) {
    asm("fma.rn.f32x2 %0, %1, %2, %0;" : "+l"(d) : "l"(a), "l"(b));
}
__device__ __forceinline__ ull pk(float a, float b) {
    ull r; asm("mov.b64 %0, {%1, %2};" : "=l"(r) : "f"(a), "f"(b)); return r;
}
__device__ __forceinline__ float2 unpk(ull v) {
    float x, y; asm("mov.b64 {%0, %1}, %2;" : "=f"(x), "=f"(y) : "l"(v));
    return make_float2(x, y);
}

// =====================================================================
// Phase 1: xp[t,b,h] = sum_i x[t,b,i] * W_ih[h,i] + b_ih[h] + b_hh[h]
// One CTA per t. 256 threads. Output tile 64(b) x 256(h).
// =====================================================================
__global__ __launch_bounds__(256) void xp_gemm_kernel(
    const float* __restrict__ x,    // [SEQ][BATCH][INP]
    const float* __restrict__ Wih,  // [HID][INP]
    const float* __restrict__ bih,  // [HID]
    const float* __restrict__ bhh,  // [HID]
    float* __restrict__ out)        // [SEQ][BATCH][HID]
{
    __shared__ float Xs[32][68];
    __shared__ float Ws[32][257];

    const int t   = blockIdx.x;
    const int tid = threadIdx.x;
    const int tn  = tid & 31;
    const int tm  = tid >> 5;
    const int m0  = tm * 8;

    const float* xt = x + (size_t)t * BATCH * INP;

    ull acc[8][4];
    #pragma unroll
    for (int u = 0; u < 8; ++u)
        #pragma unroll
        for (int v = 0; v < 4; ++v) acc[u][v] = 0ull;

    for (int kc = 0; kc < INP; kc += 32) {
        #pragma unroll
        for (int r = 0; r < 2; ++r) {
            int idx = tid + 256 * r;
            int m   = idx >> 3;
            int k4  = (idx & 7) * 4;
            float4 v = *(const float4*)(xt + (size_t)m * INP + kc + k4);
            Xs[k4 + 0][m] = v.x; Xs[k4 + 1][m] = v.y;
            Xs[k4 + 2][m] = v.z; Xs[k4 + 3][m] = v.w;
        }
        #pragma unroll
        for (int r = 0; r < 8; ++r) {
            int idx = tid + 256 * r;
            int h   = idx >> 3;
            int k4  = (idx & 7) * 4;
            float4 v = *(const float4*)(Wih + (size_t)h * INP + kc + k4);
            Ws[k4 + 0][h] = v.x; Ws[k4 + 1][h] = v.y;
            Ws[k4 + 2][h] = v.z; Ws[k4 + 3][h] = v.w;
        }
        __syncthreads();

        #pragma unroll
        for (int k = 0; k < 32; ++k) {
            float4 a0 = *(const float4*)&Xs[k][m0];
            float4 a1 = *(const float4*)&Xs[k][m0 + 4];
            ull ap[8];
            ap[0] = pk(a0.x, a0.x); ap[1] = pk(a0.y, a0.y);
            ap[2] = pk(a0.z, a0.z); ap[3] = pk(a0.w, a0.w);
            ap[4] = pk(a1.x, a1.x); ap[5] = pk(a1.y, a1.y);
            ap[6] = pk(a1.z, a1.z); ap[7] = pk(a1.w, a1.w);

            float w[8];
            #pragma unroll
            for (int v = 0; v < 8; ++v) w[v] = Ws[k][tn + 32 * v];

            #pragma unroll
            for (int v2 = 0; v2 < 4; ++v2) {
                ull wp = pk(w[2 * v2], w[2 * v2 + 1]);
                #pragma unroll
                for (int u = 0; u < 8; ++u)
                    ffma2(acc[u][v2], wp, ap[u]);
            }
        }
        __syncthreads();
    }

    float ba[4], bb[4];
    #pragma unroll
    for (int v2 = 0; v2 < 4; ++v2) {
        int hA = tn + 64 * v2, hB = hA + 32;
        ba[v2] = bih[hA] + bhh[hA];
        bb[v2] = bih[hB] + bhh[hB];
    }
    float* ot = out + (size_t)t * BATCH * HID;
    #pragma unroll
    for (int u = 0; u < 8; ++u) {
        float* row = ot + (size_t)(m0 + u) * HID;
        #pragma unroll
        for (int v2 = 0; v2 < 4; ++v2) {
            float2 s = unpk(acc[u][v2]);
            row[tn + 64 * v2]      = s.x + ba[v2];
            row[tn + 64 * v2 + 32] = s.y + bb[v2];
        }
    }
}

// =====================================================================
// Phase 2: serial scan, v2.
// 64 CTAs (one per batch), 512 threads. Thread 2j+s computes the
// half dot-product of output row j over k in [128s, 128s+128):
//   - first 96 k-values from 48 register-resident f32x2 pairs
//   - last  32 k-values from smem W (layout [g][tid] -> coalesced LDS.128)
// Halves combine via shfl_xor(1); ONE __syncthreads per step.
// h double-buffered in smem with +4 float padding at the 128 boundary
// so the two lane-parity address streams hit disjoint banks.
// =====================================================================
#define RKP   48                  // register W pairs per thread (96 floats)
#define RK    (2 * RKP)           // 96
#define SK    (128 - RK)          // 32 smem k-values per thread
#define SG    (SK / 4)            // 8 ulonglong2 groups per thread
#define HPAD  132                 // padded offset of h[128..] stream (floats)
#define HBUF  264                 // floats per h buffer

__global__ __launch_bounds__(512, 1) void rnn_scan_kernel(
    const float* __restrict__ Whh,  // [HID][HID]
    float* __restrict__ out)        // in: xp, out: h   [SEQ][BATCH][HID]
{
    extern __shared__ float smem[];
    // [ Wsm: SG*512 ulonglong2 = 64KB ][ hbuf: 2*HBUF floats ]
    ulonglong2* Wsm  = (ulonglong2*)smem;
    float*      hbuf = smem + SG * 512 * 4;

    const int b   = blockIdx.x;
    const int tid = threadIdx.x;
    const int j   = tid >> 1;     // output row 0..255
    const int s   = tid & 1;      // k-half

    const float* wrow = Whh + (size_t)j * HID + s * 128;

    // ---- register-resident W slice: k in [128s, 128s+96) ----
    ull wreg[RKP];
    #pragma unroll
    for (int p = 0; p < RKP; ++p)
        wreg[p] = *(const ull*)(wrow + 2 * p);

    // ---- smem-resident W slice: k in [128s+96, 128s+128) ----
    #pragma unroll
    for (int g = 0; g < SG; ++g) {
        float4 v = *(const float4*)(wrow + RK + 4 * g);
        ulonglong2 u;
        u.x = pk(v.x, v.y); u.y = pk(v.z, v.w);
        Wsm[g * 512 + tid] = u;
    }

    // ---- h0 = 0 ----
    hbuf[tid] = 0.f;
    if (tid < 2 * HBUF - 512) hbuf[512 + tid] = 0.f;
    __syncthreads();

    const size_t stride = (size_t)BATCH * HID;
    float* col = out + (size_t)b * HID + j;   // valid for s==0 writers

    float xpv = (s == 0) ? col[0] : 0.f;
    int cur = 0;

    const int hoff = s * HPAD;                // this thread's h stream base
    const int jpos = j + ((j >> 7) << 2);     // padded position of h[j]

    for (int t = 0; t < SEQ; ++t) {
        float xp_next = 0.f;
        if (s == 0 && t + 1 < SEQ)
            xp_next = __ldcg(col + (size_t)(t + 1) * stride);

        const ulonglong2* h2 = (const ulonglong2*)(hbuf + cur * HBUF + hoff);
        ull acc0 = 0ull, acc1 = 0ull;

        #pragma unroll
        for (int g = 0; g < RKP / 2; ++g) {       // register W part (k 0..95)
            ulonglong2 h = h2[g];
            ffma2(acc0, wreg[2 * g],     h.x);
            ffma2(acc1, wreg[2 * g + 1], h.y);
        }
        #pragma unroll
        for (int g = 0; g < SG; ++g) {            // smem W part (k 96..127)
            ulonglong2 w = Wsm[g * 512 + tid];
            ulonglong2 h = h2[RKP / 2 + g];
            ffma2(acc0, w.x, h.x);
            ffma2(acc1, w.y, h.y);
        }

        float2 s0 = unpk(acc0), s1 = unpk(acc1);
        float part = (s0.x + s0.y) + (s1.x + s1.y);
        float other = __shfl_xor_sync(0xFFFFFFFFu, part, 1);
        float val = tanhf(xpv + part + other);

        if (s == 0) {
            col[(size_t)t * stride] = val;               // h_t -> gmem
            hbuf[(cur ^ 1) * HBUF + jpos] = val;         // h_t -> next buffer
        }
        __syncthreads();
        cur ^= 1;
        xpv = xp_next;
    }
}

// =====================================================================
extern "C" void kernel_launch(void* const* d_in, const int* in_sizes, int n_in,
                              void* d_out, int out_size) {
    const float* x   = (const float*)d_in[0];  // [SEQ][BATCH][INP]
    const float* Wih = (const float*)d_in[1];  // [HID][INP]
    const float* Whh = (const float*)d_in[2];  // [HID][HID]
    const float* bih = (const float*)d_in[3];  // [HID]
    const float* bhh = (const float*)d_in[4];  // [HID]
    float* out = (float*)d_out;                // [SEQ][BATCH][HID]

    static int smem_set = 0;
    const int scan_smem = SG * 512 * 16 + 2 * HBUF * 4;  // 65536 + 2112 B
    if (!smem_set) {
        cudaFuncSetAttribute(rnn_scan_kernel,
                             cudaFuncAttributeMaxDynamicSharedMemorySize,
                             scan_smem);
        smem_set = 1;
    }

    xp_gemm_kernel<<<SEQ, 256>>>(x, Wih, bih, bhh, out);
    rnn_scan_kernel<<<BATCH, 512, scan_smem>>>(Whh, out);
}

// round 5
// speedup vs baseline: 1.1061x; 1.1061x over previous
#include <cuda_runtime.h>
#include <cstdint>
#include <math.h>

#define SEQ   2048
#define BATCH 64
#define INP   256
#define HID   256

typedef unsigned long long ull;

// ---------- packed f32x2 helpers (Blackwell FFMA2 path, PTX-only) ----------
__device__ __forceinline__ void ffma2(ull& d, ull a, ull b) {
    asm("fma.rn.f32x2 %0, %1, %2, %0;" : "+l"(d) : "l"(a), "l"(b));
}
__device__ __forceinline__ ull pk(float a, float b) {
    ull r; asm("mov.b64 %0, {%1, %2};" : "=l"(r) : "f"(a), "f"(b)); return r;
}
__device__ __forceinline__ float2 unpk(ull v) {
    float x, y; asm("mov.b64 {%0, %1}, %2;" : "=f"(x), "=f"(y) : "l"(v));
    return make_float2(x, y);
}

__device__ __forceinline__ unsigned smem_u32(const void* p) {
    unsigned a;
    asm("{ .reg .u64 t; cvta.to.shared.u64 t, %1; cvt.u32.u64 %0, t; }"
        : "=r"(a) : "l"(p));
    return a;
}
__device__ __forceinline__ unsigned mapa_peer(unsigned local_addr, unsigned peer) {
    unsigned r;
    asm("mapa.shared::cluster.u32 %0, %1, %2;" : "=r"(r) : "r"(local_addr), "r"(peer));
    return r;
}

// =====================================================================
// Phase 1: xp[t,b,h] = sum_i x[t,b,i] * W_ih[h,i] + b_ih[h] + b_hh[h]
// One CTA per t. 256 threads. (unchanged from R2 — ~350us)
// =====================================================================
__global__ __launch_bounds__(256) void xp_gemm_kernel(
    const float* __restrict__ x,
    const float* __restrict__ Wih,
    const float* __restrict__ bih,
    const float* __restrict__ bhh,
    float* __restrict__ out)
{
    __shared__ float Xs[32][68];
    __shared__ float Ws[32][257];

    const int t   = blockIdx.x;
    const int tid = threadIdx.x;
    const int tn  = tid & 31;
    const int tm  = tid >> 5;
    const int m0  = tm * 8;

    const float* xt = x + (size_t)t * BATCH * INP;

    ull acc[8][4];
    #pragma unroll
    for (int u = 0; u < 8; ++u)
        #pragma unroll
        for (int v = 0; v < 4; ++v) acc[u][v] = 0ull;

    for (int kc = 0; kc < INP; kc += 32) {
        #pragma unroll
        for (int r = 0; r < 2; ++r) {
            int idx = tid + 256 * r;
            int m   = idx >> 3;
            int k4  = (idx & 7) * 4;
            float4 v = *(const float4*)(xt + (size_t)m * INP + kc + k4);
            Xs[k4 + 0][m] = v.x; Xs[k4 + 1][m] = v.y;
            Xs[k4 + 2][m] = v.z; Xs[k4 + 3][m] = v.w;
        }
        #pragma unroll
        for (int r = 0; r < 8; ++r) {
            int idx = tid + 256 * r;
            int h   = idx >> 3;
            int k4  = (idx & 7) * 4;
            float4 v = *(const float4*)(Wih + (size_t)h * INP + kc + k4);
            Ws[k4 + 0][h] = v.x; Ws[k4 + 1][h] = v.y;
            Ws[k4 + 2][h] = v.z; Ws[k4 + 3][h] = v.w;
        }
        __syncthreads();

        #pragma unroll
        for (int k = 0; k < 32; ++k) {
            float4 a0 = *(const float4*)&Xs[k][m0];
            float4 a1 = *(const float4*)&Xs[k][m0 + 4];
            ull ap[8];
            ap[0] = pk(a0.x, a0.x); ap[1] = pk(a0.y, a0.y);
            ap[2] = pk(a0.z, a0.z); ap[3] = pk(a0.w, a0.w);
            ap[4] = pk(a1.x, a1.x); ap[5] = pk(a1.y, a1.y);
            ap[6] = pk(a1.z, a1.z); ap[7] = pk(a1.w, a1.w);

            float w[8];
            #pragma unroll
            for (int v = 0; v < 8; ++v) w[v] = Ws[k][tn + 32 * v];

            #pragma unroll
            for (int v2 = 0; v2 < 4; ++v2) {
                ull wp = pk(w[2 * v2], w[2 * v2 + 1]);
                #pragma unroll
                for (int u = 0; u < 8; ++u)
                    ffma2(acc[u][v2], wp, ap[u]);
            }
        }
        __syncthreads();
    }

    float ba[4], bb[4];
    #pragma unroll
    for (int v2 = 0; v2 < 4; ++v2) {
        int hA = tn + 64 * v2, hB = hA + 32;
        ba[v2] = bih[hA] + bhh[hA];
        bb[v2] = bih[hB] + bhh[hB];
    }
    float* ot = out + (size_t)t * BATCH * HID;
    #pragma unroll
    for (int u = 0; u < 8; ++u) {
        float* row = ot + (size_t)(m0 + u) * HID;
        #pragma unroll
        for (int v2 = 0; v2 < 4; ++v2) {
            float2 s = unpk(acc[u][v2]);
            row[tn + 64 * v2]      = s.x + ba[v2];
            row[tn + 64 * v2 + 32] = s.y + bb[v2];
        }
    }
}

// =====================================================================
// Phase 2: serial scan, v3 — 2-CTA cluster per batch.
// grid = 128 CTAs (cluster (2,1,1)), 512 threads.
// Cluster for batch b = CTAs {2b, 2b+1}; rank r owns k in [128r,128r+128)
// and finalizes rows [128r, 128r+128).
// Thread tid=2j+s: output row j (0..255), k in [128r+64s, +64).
// All 64 W values in registers (32 ull). h (128 floats, local rows only)
// double-buffered in smem, broadcast reads.
// Per step: partials for peer's 128 rows go over DSMEM (512B) guarded by
// an mbarrier (count=128, release-arrive per sender, acquire try_wait).
// =====================================================================
#define WK    64               // k-values per thread
#define WKP   (WK / 2)         // 32 ull pairs
#define HPAD  68               // padded stride of the s=1 h stream (floats)
#define HBUF  (HPAD + 64)      // 132 floats per h buffer

__global__ __launch_bounds__(512, 1) __cluster_dims__(2, 1, 1)
void rnn_scan_kernel(
    const float* __restrict__ Whh,  // [HID][HID]
    float* __restrict__ out)        // in: xp, out: h   [SEQ][BATCH][HID]
{
    __shared__ float hbuf[2 * HBUF];        // local rows' h, double buffered
    __shared__ float recvbuf[2 * 128];      // peer partials, double buffered
    __shared__ alignas(8) ull mbar[2];

    const int bidx = blockIdx.x;
    const int b    = bidx >> 1;
    const int r    = bidx & 1;              // == cluster rank
    const int tid  = threadIdx.x;
    const int j    = tid >> 1;              // global output row
    const int s    = tid & 1;               // k-quarter within my half

    const int mine   = (j >> 7) == r;       // do I finalize row j?
    const int jj     = j & 127;             // local row index (both roles)

    // ---- register-resident W: W_hh[j][128r + 64s + 0..63] ----
    ull wreg[WKP];
    {
        const float* wrow = Whh + (size_t)j * HID + r * 128 + s * 64;
        #pragma unroll
        for (int p = 0; p < WKP; ++p)
            wreg[p] = *(const ull*)(wrow + 2 * p);
    }

    // ---- init smem ----
    if (tid < 2 * HBUF) hbuf[tid] = 0.f;
    if (tid == 0) {
        asm volatile("mbarrier.init.shared.b64 [%0], %1;"
                     :: "r"(smem_u32(&mbar[0])), "r"(128) : "memory");
        asm volatile("mbarrier.init.shared.b64 [%0], %1;"
                     :: "r"(smem_u32(&mbar[1])), "r"(128) : "memory");
    }
    __syncthreads();
    // all mbarriers across the cluster initialized before any arrive:
    asm volatile("barrier.cluster.arrive.aligned;" ::: "memory");
    asm volatile("barrier.cluster.wait.aligned;"   ::: "memory");

    // ---- peer addresses (computed once) ----
    const unsigned peer       = (unsigned)(r ^ 1);
    const unsigned recv_l     = smem_u32(recvbuf);
    const unsigned mbar_l0    = smem_u32(&mbar[0]);
    const unsigned mbar_l1    = smem_u32(&mbar[1]);
    const unsigned peer_recv  = mapa_peer(recv_l, peer);
    const unsigned peer_mbar0 = mapa_peer(mbar_l0, peer);
    const unsigned peer_mbar1 = mapa_peer(mbar_l1, peer);

    const size_t stride = (size_t)BATCH * HID;
    float* col = out + (size_t)b * HID + j;     // xp/h column for row j

    float xpv = mine ? __ldcg(col) : 0.f;
    int cur = 0;

    const int hoff = s * HPAD;                  // my h read stream base

    for (int t = 0; t < SEQ; ++t) {
        // ---- matvec partial over my 64 k-values ----
        const ulonglong2* h2 = (const ulonglong2*)(hbuf + cur * HBUF + hoff);
        ull acc0 = 0ull, acc1 = 0ull;
        #pragma unroll
        for (int g = 0; g < WKP / 2; ++g) {     // 16 x (2 ffma2)
            ulonglong2 h = h2[g];
            ffma2(acc0, wreg[2 * g],     h.x);
            ffma2(acc1, wreg[2 * g + 1], h.y);
        }
        float2 s0 = unpk(acc0), s1 = unpk(acc1);
        float part = (s0.x + s0.y) + (s1.x + s1.y);
        float tot  = part + __shfl_xor_sync(0xFFFFFFFFu, part, 1);
        // tot = full partial of row j over k in [128r, 128r+128)

        const unsigned mb_sel = (unsigned)(t & 1);
        if (!mine) {
            // send partial to peer (it finalizes row j), then release-arrive
            if (s == 0) {
                unsigned a = peer_recv + mb_sel * 512u + (unsigned)jj * 4u;
                asm volatile("st.shared::cluster.f32 [%0], %1;"
                             :: "r"(a), "f"(tot) : "memory");
                asm volatile("mbarrier.arrive.release.cluster.shared::cluster.b64 _, [%0];"
                             :: "r"(mb_sel ? peer_mbar1 : peer_mbar0) : "memory");
            }
        } else {
            // wait for peer's 128 partials for this step
            {
                const unsigned mb  = mb_sel ? mbar_l1 : mbar_l0;
                const unsigned par = (unsigned)((t >> 1) & 1);
                unsigned done;
                asm volatile(
                    "{\n\t.reg .pred p;\n\t"
                    "mbarrier.try_wait.parity.acquire.cluster.shared::cta.b64 p, [%1], %2;\n\t"
                    "selp.b32 %0, 1, 0, p;\n\t}"
                    : "=r"(done) : "r"(mb), "r"(par) : "memory");
                while (!done) {
                    asm volatile(
                        "{\n\t.reg .pred p;\n\t"
                        "mbarrier.try_wait.parity.acquire.cluster.shared::cta.b64 p, [%1], %2;\n\t"
                        "selp.b32 %0, 1, 0, p;\n\t}"
                        : "=r"(done) : "r"(mb), "r"(par) : "memory");
                }
            }
            float peer_part = recvbuf[mb_sel * 128 + jj];
            float val = tanhf(xpv + tot + peer_part);

            if (s == 0) {
                // h for next step (padded layout: stream s' = jj>=64)
                hbuf[(cur ^ 1) * HBUF + ((jj < 64) ? jj : (jj - 64 + HPAD))] = val;
            } else {
                col[(size_t)t * stride] = val;          // h_t -> gmem
            }
            // both lanes prefetch next xp
            if (t + 1 < SEQ) xpv = __ldcg(col + (size_t)(t + 1) * stride);
        }

        __syncthreads();
        cur ^= 1;
    }

    // no CTA exits while peer traffic could be in flight
    asm volatile("barrier.cluster.arrive.aligned;" ::: "memory");
    asm volatile("barrier.cluster.wait.aligned;"   ::: "memory");
}

// =====================================================================
extern "C" void kernel_launch(void* const* d_in, const int* in_sizes, int n_in,
                              void* d_out, int out_size) {
    const float* x   = (const float*)d_in[0];  // [SEQ][BATCH][INP]
    const float* Wih = (const float*)d_in[1];  // [HID][INP]
    const float* Whh = (const float*)d_in[2];  // [HID][HID]
    const float* bih = (const float*)d_in[3];  // [HID]
    const float* bhh = (const float*)d_in[4];  // [HID]
    float* out = (float*)d_out;                // [SEQ][BATCH][HID]

    xp_gemm_kernel<<<SEQ, 256>>>(x, Wih, bih, bhh, out);
    rnn_scan_kernel<<<2 * BATCH, 512>>>(Whh, out);
}